// round 9
// baseline (speedup 1.0000x reference)
#include <cuda_runtime.h>

// SNN recurrence: B=1024, T=1024, H=32, I=2.
// One warp per batch, one lane per hidden unit, scalar fp32, bit-exact
// reference-order rounding (rel_err = 0.0 across all prior rounds).
//
// R9: the fma pipe is the measured bottleneck (10 rt=2 ops/step/warp => 40
// cyc/step floor at 2 warps/SMSP). Every FADD is replaced by an FFMA with an
// IMMEDIATE 1.0 multiplier (SASS 0x823 form, rt_SMSP=1, half the pipe cost):
//     add.rn(a, b) == fma.rn(a, 1.0imm, b)    (bit-exact: a*1.0 is exact)
// Pipe cost drops to 5*2 + 5*1 = 15 cyc/warp/step -> 30 cyc/step floor.
// Conditional resets/injections stay predicated (alu-pipe setp, no FSELs).

#define TT 1024

__device__ __forceinline__ float fadd1(float a, float b) {
    // a + b as FFMA a*1.0+b with immediate multiplier (rt=1 form), bit-exact
    float r;
    asm("fma.rn.f32 %0, %1, 0f3F800000, %2;" : "=f"(r) : "f"(a), "f"(b));
    return r;
}

__device__ __forceinline__ float uterm(float2 xv, float w0, float w1, float bg) {
    // bg*(x0*w0 + x1*w1), reference rounding order (add via imm-FFMA)
    return __fmul_rn(bg, fadd1(__fmul_rn(xv.x, w0), __fmul_rn(xv.y, w1)));
}

__device__ __forceinline__ void step_plain(float& v, float& V, float u,
                                           float ag, float as, float bs,
                                           float negone) {
    asm("{\n\t"
        ".reg .pred p, q;\n\t"
        "setp.gt.f32 p, %0, 0f3F800000;\n\t"            // s_{t-1} = v > 1
        "setp.gt.f32 q, %1, 0f3F800000;\n\t"            // S_{t-1} = V > 1
        "mul.rn.f32 %0, %0, %3;\n\t"                    // v = ag*v
        "fma.rn.f32 %0, %0, 0f3F800000, %2;\n\t"        // v += u      (imm-FFMA)
        "@p fma.rn.f32 %0, %0, 0f3F800000, %6;\n\t"     // v += -1     (reset)
        "setp.gt.f32 p, %0, 0f3F800000;\n\t"            // s_t = v > 1
        "mul.rn.f32 %1, %1, %4;\n\t"                    // V = as*V
        "@p fma.rn.f32 %1, %1, 0f3F800000, %5;\n\t"     // V += bs     (inject)
        "@q fma.rn.f32 %1, %1, 0f3F800000, %6;\n\t"     // V += -1     (reset)
        "}"
        : "+f"(v), "+f"(V)
        : "f"(u), "f"(ag), "f"(as), "f"(bs), "f"(negone));
}

__device__ __forceinline__ void step_acc(float& v, float& V, int& acc, float u,
                                         float ag, float as, float bs,
                                         float negone) {
    asm("{\n\t"
        ".reg .pred p, q;\n\t"
        "setp.gt.f32 p, %0, 0f3F800000;\n\t"
        "setp.gt.f32 q, %1, 0f3F800000;\n\t"
        "mul.rn.f32 %0, %0, %4;\n\t"
        "fma.rn.f32 %0, %0, 0f3F800000, %3;\n\t"
        "@p fma.rn.f32 %0, %0, 0f3F800000, %7;\n\t"
        "setp.gt.f32 p, %0, 0f3F800000;\n\t"
        "mul.rn.f32 %1, %1, %5;\n\t"
        "@p fma.rn.f32 %1, %1, 0f3F800000, %6;\n\t"
        "@q fma.rn.f32 %1, %1, 0f3F800000, %7;\n\t"
        "setp.gt.f32 q, %1, 0f3F800000;\n\t"            // S_t
        "@q add.s32 %2, %2, 1;\n\t"                     // spike count (alu)
        "}"
        : "+f"(v), "+f"(V), "+r"(acc)
        : "f"(u), "f"(ag), "f"(as), "f"(bs), "f"(negone));
}

template <bool ACC>
__device__ __forceinline__ void run32(const float2* __restrict__ buf,
                                      float& v, float& V, int& acc,
                                      float w0, float w1, float ag, float bg,
                                      float as, float bs, float negone)
{
    float u = uterm(buf[0], w0, w1, bg);   // LDS exposed once per chunk
    #pragma unroll
    for (int i = 0; i < 32; ++i) {
        float un = 0.0f;
        if (i < 31) un = uterm(buf[i + 1], w0, w1, bg);  // off-chain prefetch
        if (ACC) step_acc(v, V, acc, u, ag, as, bs, negone);
        else     step_plain(v, V, u, ag, as, bs, negone);
        u = un;
    }
}

__global__ __launch_bounds__(256, 1)
void snn_kernel(const float* __restrict__ x,
                const float* __restrict__ Wg,     // [32,2]
                const float* __restrict__ tau_g,  // [32]
                const float* __restrict__ tau_s,  // [32]
                const float* __restrict__ Wout,   // [32]
                const float* __restrict__ bout,   // [1]
                float* __restrict__ out)          // [1024]
{
    const int lane = threadIdx.x & 31;
    const int wib  = threadIdx.x >> 5;
    const int b    = blockIdx.x * 8 + wib;

    __shared__ float2 sbuf[8][2][32];   // [warp-in-block][double buffer][step]

    const float w0 = Wg[2 * lane];
    const float w1 = Wg[2 * lane + 1];
    const float ag = 1.0f / (1.0f + expf(-tau_g[lane]));
    const float bg = 1.0f - ag;
    const float as = 1.0f / (1.0f + expf(-tau_s[lane]));
    const float bs = 1.0f - as;
    // -1.0 kept in a register (imm-FFMA form needs the addend in a register)
    float negone;
    asm("mov.f32 %0, 0fBF800000;" : "=f"(negone));

    const float2* xp = reinterpret_cast<const float2*>(x) + (size_t)b * TT;

    float v = 0.0f, V = 0.0f;
    int acc = 0;

    // Prime buffer 0
    float2 nxt = xp[lane];
    sbuf[wib][0][lane] = nxt;
    __syncwarp();
    int cur = 0;

    #pragma unroll 1
    for (int chunk = 0; chunk < 24; ++chunk) {
        nxt = xp[(chunk + 1) * 32 + lane];          // GMEM prefetch next chunk
        run32<false>(sbuf[wib][cur], v, V, acc, w0, w1, ag, bg, as, bs, negone);
        sbuf[wib][cur ^ 1][lane] = nxt;
        __syncwarp();
        cur ^= 1;
    }
    #pragma unroll 1
    for (int chunk = 24; chunk < 32; ++chunk) {
        if (chunk + 1 < 32) nxt = xp[(chunk + 1) * 32 + lane];
        run32<true>(sbuf[wib][cur], v, V, acc, w0, w1, ag, bg, as, bs, negone);
        if (chunk + 1 < 32) sbuf[wib][cur ^ 1][lane] = nxt;
        __syncwarp();
        cur ^= 1;
    }

    // out[b] = sum_h acc_h * Wout[h] + bout  (identical reduction tree)
    float val = __fmul_rn((float)acc, Wout[lane]);
    #pragma unroll
    for (int off = 16; off; off >>= 1)
        val += __shfl_xor_sync(0xffffffffu, val, off);
    if (lane == 0) out[b] = val + bout[0];
}

extern "C" void kernel_launch(void* const* d_in, const int* in_sizes, int n_in,
                              void* d_out, int out_size) {
    const float* x    = (const float*)d_in[0];
    const float* Wg   = (const float*)d_in[1];
    const float* taug = (const float*)d_in[2];
    const float* taus = (const float*)d_in[3];
    const float* Wout = (const float*)d_in[4];
    const float* bout = (const float*)d_in[5];
    float* out = (float*)d_out;

    // 1024 warps, uniform 2 warps/SMSP on 128 SMs: 128 blocks x 256 threads
    snn_kernel<<<128, 256>>>(x, Wg, taug, taus, Wout, bout, out);
}

// round 10
// speedup vs baseline: 1.0196x; 1.0196x over previous
#include <cuda_runtime.h>

// SNN recurrence: B=1024, T=1024, H=32, I=2. One warp/batch, one lane/unit.
// Bit-exact reference-order rounding (rel_err = 0.0 across all prior rounds).
//
// R10: the fma pipe is the measured wall (10 rt=2 ops/step/warp = 40 cyc/
// step-pair at 2 warps/SMSP; bench = 41). All five FADDs become FFMA-imm
// (SASS 0x823, rt=1) in a peephole-PROOF way: multiplier imm = 0.5 with
// pre-doubled companion constants (2w0, 2bg, 2bs, -2.0-from-memory).
// Rounding commutes with exact x2 scaling and FMA's product is exact, so
// every rounding event is bit-identical to the proven sequence:
//   round(x0*2w0)*0.5 == round(x0*w0); fma(u2,0.5,agv) == round(u+agv); etc.
// New pipe floor: 5*2 + 5*1 = 15 cyc/warp/step -> 30 cyc/step-pair.

#define TT 1024

__device__ float g_negtwo = -2.0f;   // opaque -2.0 (defeats const-prop)

__device__ __forceinline__ float uterm2(float2 xv, float W0d, float w1, float BG2) {
    // returns 2*u where u = bg*(x0*w0 + x1*w1), all roundings == reference
    float t0 = __fmul_rn(xv.x, W0d);               // round(x0*2w0) = 2*round(x0*w0)
    float t1 = __fmul_rn(xv.y, w1);                // round(x1*w1)
    float gi = __fmaf_rn(t0, 0.5f, t1);            // round(x0w0 + x1w1)  [FFMA-imm]
    return __fmul_rn(BG2, gi);                     // 2*round(bg*gi)
}

__device__ __forceinline__ void step_plain(float& v, float& V, float u2,
                                           float ag, float as, float BS2,
                                           float negtwo) {
    asm("{\n\t"
        ".reg .pred p, q;\n\t"
        "setp.gt.f32 p, %0, 0f3F800000;\n\t"          // s_{t-1} = v > 1
        "setp.gt.f32 q, %1, 0f3F800000;\n\t"          // S_{t-1} = V > 1
        "mul.rn.f32 %0, %0, %3;\n\t"                  // v = ag*v
        "fma.rn.f32 %0, %2, 0f3F000000, %0;\n\t"      // v += u      (u2*0.5)
        "@p fma.rn.f32 %0, %6, 0f3F000000, %0;\n\t"   // v += -1    (negtwo*0.5)
        "setp.gt.f32 p, %0, 0f3F800000;\n\t"          // s_t = v > 1
        "mul.rn.f32 %1, %1, %4;\n\t"                  // V = as*V
        "@p fma.rn.f32 %1, %5, 0f3F000000, %1;\n\t"   // V += bs    (BS2*0.5)
        "@q fma.rn.f32 %1, %6, 0f3F000000, %1;\n\t"   // V += -1
        "}"
        : "+f"(v), "+f"(V)
        : "f"(u2), "f"(ag), "f"(as), "f"(BS2), "f"(negtwo));
}

__device__ __forceinline__ void step_acc(float& v, float& V, int& acc, float u2,
                                         float ag, float as, float BS2,
                                         float negtwo) {
    asm("{\n\t"
        ".reg .pred p, q;\n\t"
        "setp.gt.f32 p, %0, 0f3F800000;\n\t"
        "setp.gt.f32 q, %1, 0f3F800000;\n\t"
        "mul.rn.f32 %0, %0, %4;\n\t"
        "fma.rn.f32 %0, %3, 0f3F000000, %0;\n\t"
        "@p fma.rn.f32 %0, %7, 0f3F000000, %0;\n\t"
        "setp.gt.f32 p, %0, 0f3F800000;\n\t"
        "mul.rn.f32 %1, %1, %5;\n\t"
        "@p fma.rn.f32 %1, %6, 0f3F000000, %1;\n\t"
        "@q fma.rn.f32 %1, %7, 0f3F000000, %1;\n\t"
        "setp.gt.f32 q, %1, 0f3F800000;\n\t"          // S_t
        "@q add.s32 %2, %2, 1;\n\t"                   // spike count (alu pipe)
        "}"
        : "+f"(v), "+f"(V), "+r"(acc)
        : "f"(u2), "f"(ag), "f"(as), "f"(BS2), "f"(negtwo));
}

template <bool ACC>
__device__ __forceinline__ void run32(const float2* __restrict__ buf,
                                      float& v, float& V, int& acc,
                                      float W0d, float w1, float ag, float BG2,
                                      float as, float BS2, float negtwo)
{
    float u2 = uterm2(buf[0], W0d, w1, BG2);   // LDS exposed once per chunk
    #pragma unroll
    for (int i = 0; i < 32; ++i) {
        float un = 0.0f;
        if (i < 31) un = uterm2(buf[i + 1], W0d, w1, BG2);  // off-chain prefetch
        if (ACC) step_acc(v, V, acc, u2, ag, as, BS2, negtwo);
        else     step_plain(v, V, u2, ag, as, BS2, negtwo);
        u2 = un;
    }
}

__global__ __launch_bounds__(256, 1)
void snn_kernel(const float* __restrict__ x,
                const float* __restrict__ Wg,     // [32,2]
                const float* __restrict__ tau_g,  // [32]
                const float* __restrict__ tau_s,  // [32]
                const float* __restrict__ Wout,   // [32]
                const float* __restrict__ bout,   // [1]
                float* __restrict__ out)          // [1024]
{
    const int lane = threadIdx.x & 31;
    const int wib  = threadIdx.x >> 5;
    const int b    = blockIdx.x * 8 + wib;

    __shared__ float2 sbuf[8][2][32];   // [warp-in-block][double buffer][step]

    const float w0 = Wg[2 * lane];
    const float w1 = Wg[2 * lane + 1];
    const float ag = 1.0f / (1.0f + expf(-tau_g[lane]));
    const float bg = 1.0f - ag;
    const float as = 1.0f / (1.0f + expf(-tau_s[lane]));
    const float bs = 1.0f - as;

    const float W0d = 2.0f * w0;      // exact scalings (power of 2)
    const float BG2 = 2.0f * bg;
    const float BS2 = 2.0f * bs;
    const float negtwo = g_negtwo;    // opaque -2.0 (from device global)

    const float2* xp = reinterpret_cast<const float2*>(x) + (size_t)b * TT;

    float v = 0.0f, V = 0.0f;
    int acc = 0;

    // Prime buffer 0
    float2 nxt = xp[lane];
    sbuf[wib][0][lane] = nxt;
    __syncwarp();
    int cur = 0;

    #pragma unroll 1
    for (int chunk = 0; chunk < 24; ++chunk) {
        nxt = xp[(chunk + 1) * 32 + lane];          // GMEM prefetch next chunk
        run32<false>(sbuf[wib][cur], v, V, acc, W0d, w1, ag, BG2, as, BS2, negtwo);
        sbuf[wib][cur ^ 1][lane] = nxt;
        __syncwarp();
        cur ^= 1;
    }
    #pragma unroll 1
    for (int chunk = 24; chunk < 32; ++chunk) {
        if (chunk + 1 < 32) nxt = xp[(chunk + 1) * 32 + lane];
        run32<true>(sbuf[wib][cur], v, V, acc, W0d, w1, ag, BG2, as, BS2, negtwo);
        if (chunk + 1 < 32) sbuf[wib][cur ^ 1][lane] = nxt;
        __syncwarp();
        cur ^= 1;
    }

    // out[b] = sum_h acc_h * Wout[h] + bout  (identical reduction tree)
    float val = __fmul_rn((float)acc, Wout[lane]);
    #pragma unroll
    for (int off = 16; off; off >>= 1)
        val += __shfl_xor_sync(0xffffffffu, val, off);
    if (lane == 0) out[b] = val + bout[0];
}

extern "C" void kernel_launch(void* const* d_in, const int* in_sizes, int n_in,
                              void* d_out, int out_size) {
    const float* x    = (const float*)d_in[0];
    const float* Wg   = (const float*)d_in[1];
    const float* taug = (const float*)d_in[2];
    const float* taus = (const float*)d_in[3];
    const float* Wout = (const float*)d_in[4];
    const float* bout = (const float*)d_in[5];
    float* out = (float*)d_out;

    // 1024 warps, uniform 2 warps/SMSP on 128 SMs: 128 blocks x 256 threads
    snn_kernel<<<128, 256>>>(x, Wg, taug, taus, Wout, bout, out);
}